// round 6
// baseline (speedup 1.0000x reference)
#include <cuda_runtime.h>

// Problem constants
#define NN   50000
#define EE   600000
#define HH   128
#define LL   4
#define GG   64
#define EMBD 64
#define CC   10
#define LH   (LL*HH)        // 512
#define ZIN  (LH+EMBD)      // 576
#define H1D  256            // 2*H
#define BN_EPS 1e-5f

// ---------------- device scratch (static, allocation-guard safe) -------------
__device__ __align__(16) float g_agg[NN*HH];          // 25.6 MB
__device__ __align__(16) float g_h1[NN*HH];           // 25.6 MB
__device__ __align__(16) float g_h2[NN*HH];           // 25.6 MB
__device__ __align__(16) float g_xs[NN*LH];           // 102.4 MB (concat of layer outputs)
__device__ __align__(16) float g_bnsum[2*HH];         // per-col sum / sumsq
__device__ __align__(16) float g_pool[GG*ZIN];        // pooled sums
__device__ __align__(16) float g_cnt[GG];             // nodes per graph

// ---------------- zero kernels ----------------------------------------------
__global__ void k_zero_pool() {
    int i = blockIdx.x * blockDim.x + threadIdx.x;
    if (i < GG*ZIN) g_pool[i] = 0.f;
    if (i < GG)     g_cnt[i]  = 0.f;
}
__global__ void k_zero_bn() {
    if (threadIdx.x < 2*HH) g_bnsum[threadIdx.x] = 0.f;
}

// ---------------- agg = (1+eps_l) * x ----------------------------------------
__global__ void k_init_agg(const float* __restrict__ x, int lda,
                           const float* __restrict__ eps, int l) {
    int idx = blockIdx.x * blockDim.x + threadIdx.x;   // over NN * HH/4
    if (idx >= NN*(HH/4)) return;
    float s = 1.0f + eps[l];
    int row = idx >> 5;           // HH/4 = 32 float4 per row
    int c4  = (idx & 31) * 4;
    float4 v = *(const float4*)(x + (size_t)row*lda + c4);
    v.x *= s; v.y *= s; v.z *= s; v.w *= s;
    *(float4*)(g_agg + row*HH + c4) = v;
}

// ---------------- scatter-add: agg[dst] += x[src] (warp per edge) ------------
// edge_index is int32 (JAX default x64-disabled downcasts jnp.int64 -> int32).
__global__ void k_scatter(const float* __restrict__ x, int lda,
                          const int* __restrict__ ei) {
    int gtid = blockIdx.x * blockDim.x + threadIdx.x;
    int warp = gtid >> 5;
    int lane = gtid & 31;
    if (warp >= EE) return;
    int s = ei[warp];
    int d = ei[EE + warp];
    float4 v = *(const float4*)(x + (size_t)s*lda + lane*4);
    float* p = g_agg + (size_t)d*HH + lane*4;
    atomicAdd(p+0, v.x);
    atomicAdd(p+1, v.y);
    atomicAdd(p+2, v.z);
    atomicAdd(p+3, v.w);
}

// ---------------- SGEMM: C = relu(A[M,128] @ W[128,128] + b) -----------------
// BM=128, BN=128, BK=16, 256 threads, 8x8 per thread.
// STATS: also accumulate per-column sum/sumsq of the (post-relu) output.
template<bool STATS>
__global__ __launch_bounds__(256)
void k_gemm(const float* __restrict__ A, int lda,
            const float* __restrict__ W, const float* __restrict__ bias,
            float* __restrict__ C) {
    __shared__ __align__(16) float As[16][128];
    __shared__ __align__(16) float Bs[16][128];
    __shared__ float ssum[128], ssq[128];

    int tid = threadIdx.x;
    int blockRow = blockIdx.x * 128;

    int aRow  = tid >> 2;          // 0..63
    int aCol4 = (tid & 3) * 4;     // 0,4,8,12
    int bRow  = tid >> 5;          // 0..7
    int bCol4 = (tid & 31) * 4;    // 0..124

    int tr = (tid >> 4) * 8;       // 0..120
    int tc = (tid & 15) * 8;       // 0..120

    if (STATS && tid < 128) { ssum[tid] = 0.f; ssq[tid] = 0.f; }

    float acc[8][8];
#pragma unroll
    for (int i = 0; i < 8; i++)
#pragma unroll
        for (int j = 0; j < 8; j++) acc[i][j] = 0.f;

    for (int k0 = 0; k0 < 128; k0 += 16) {
#pragma unroll
        for (int i = 0; i < 2; i++) {
            int r = blockRow + aRow + i*64;
            float4 v = make_float4(0.f,0.f,0.f,0.f);
            if (r < NN) v = *(const float4*)(A + (size_t)r*lda + k0 + aCol4);
            As[aCol4+0][aRow + i*64] = v.x;
            As[aCol4+1][aRow + i*64] = v.y;
            As[aCol4+2][aRow + i*64] = v.z;
            As[aCol4+3][aRow + i*64] = v.w;
        }
#pragma unroll
        for (int i = 0; i < 2; i++) {
            float4 v = *(const float4*)(W + (size_t)(k0 + bRow + i*8)*128 + bCol4);
            *(float4*)(&Bs[bRow + i*8][bCol4]) = v;
        }
        __syncthreads();

#pragma unroll
        for (int k = 0; k < 16; k++) {
            float ra[8], rb[8];
            float4 a0 = *(const float4*)(&As[k][tr]);
            float4 a1 = *(const float4*)(&As[k][tr+4]);
            float4 b0 = *(const float4*)(&Bs[k][tc]);
            float4 b1 = *(const float4*)(&Bs[k][tc+4]);
            ra[0]=a0.x; ra[1]=a0.y; ra[2]=a0.z; ra[3]=a0.w;
            ra[4]=a1.x; ra[5]=a1.y; ra[6]=a1.z; ra[7]=a1.w;
            rb[0]=b0.x; rb[1]=b0.y; rb[2]=b0.z; rb[3]=b0.w;
            rb[4]=b1.x; rb[5]=b1.y; rb[6]=b1.z; rb[7]=b1.w;
#pragma unroll
            for (int i = 0; i < 8; i++)
#pragma unroll
                for (int j = 0; j < 8; j++)
                    acc[i][j] += ra[i]*rb[j];
        }
        __syncthreads();
    }

    float rbias[8];
#pragma unroll
    for (int j = 0; j < 8; j++) rbias[j] = bias[tc+j];

    float csum[8], csq[8];
#pragma unroll
    for (int j = 0; j < 8; j++) { csum[j]=0.f; csq[j]=0.f; }

#pragma unroll
    for (int i = 0; i < 8; i++) {
        int r = blockRow + tr + i;
        if (r < NN) {
#pragma unroll
            for (int j = 0; j < 8; j++) {
                float v = fmaxf(acc[i][j] + rbias[j], 0.f);
                C[(size_t)r*128 + tc + j] = v;
                if (STATS) { csum[j] += v; csq[j] += v*v; }
            }
        }
    }

    if (STATS) {
        __syncthreads();   // ssum/ssq init visible
#pragma unroll
        for (int j = 0; j < 8; j++) {
            atomicAdd(&ssum[tc+j], csum[j]);
            atomicAdd(&ssq [tc+j], csq [j]);
        }
        __syncthreads();
        if (tid < 128) {
            atomicAdd(&g_bnsum[tid],      ssum[tid]);
            atomicAdd(&g_bnsum[128+tid],  ssq [tid]);
        }
    }
}

// ---------------- BatchNorm apply + write concat slice + pooled scatter ------
__global__ void k_bn_pool(const int* __restrict__ batch,
                          const float* __restrict__ gamma,
                          const float* __restrict__ beta,
                          int l) {
    int idx = blockIdx.x * blockDim.x + threadIdx.x;  // over NN * 32
    if (idx >= NN*(HH/4)) return;
    int row = idx >> 5;
    int c4  = (idx & 31) * 4;
    const float inv = 1.0f / (float)NN;

    float4 h = *(const float4*)(g_h2 + (size_t)row*HH + c4);
    float hv[4] = {h.x, h.y, h.z, h.w};
    float vo[4];
#pragma unroll
    for (int t = 0; t < 4; t++) {
        int c = c4 + t;
        float mean = g_bnsum[c] * inv;
        float var  = g_bnsum[128+c] * inv - mean*mean;
        float rs   = rsqrtf(var + BN_EPS);
        vo[t] = (hv[t] - mean) * rs * gamma[l*HH + c] + beta[l*HH + c];
    }
    *(float4*)(g_xs + (size_t)row*LH + l*HH + c4) =
        make_float4(vo[0], vo[1], vo[2], vo[3]);

    int b = batch[row];
    float* pp = g_pool + b*ZIN + l*HH + c4;
    atomicAdd(pp+0, vo[0]);
    atomicAdd(pp+1, vo[1]);
    atomicAdd(pp+2, vo[2]);
    atomicAdd(pp+3, vo[3]);
    if (l == 0 && c4 == 0) atomicAdd(&g_cnt[b], 1.0f);
}

// ---------------- Head: MLP + log_softmax, one block per graph ---------------
__global__ __launch_bounds__(256)
void k_head(const float* __restrict__ emb,
            const float* __restrict__ l1w, const float* __restrict__ l1b,
            const float* __restrict__ l2w, const float* __restrict__ l2b,
            const float* __restrict__ l4w, const float* __restrict__ l4b,
            float* __restrict__ out) {
    __shared__ float zin[ZIN];
    __shared__ float z1[H1D];
    __shared__ float z2[HH];
    __shared__ float lg[CC];
    __shared__ float lse;

    int g = blockIdx.x, t = threadIdx.x;
    float cnt = fmaxf(g_cnt[g], 1.0f);
    for (int c = t; c < LH; c += 256) zin[c] = g_pool[g*ZIN + c] / cnt;
    if (t < EMBD) zin[LH + t] = emb[g*EMBD + t];
    __syncthreads();

    {
        float a = l1b[t];
        for (int k = 0; k < ZIN; k++) a += zin[k] * l1w[k*H1D + t];
        z1[t] = fmaxf(a, 0.f);
    }
    __syncthreads();
    if (t < HH) {
        float a = l2b[t];
        for (int k = 0; k < H1D; k++) a += z1[k] * l2w[k*HH + t];
        z2[t] = fmaxf(a, 0.f);
    }
    __syncthreads();
    if (t < CC) {
        float a = l4b[t];
        for (int k = 0; k < HH; k++) a += z2[k] * l4w[k*CC + t];
        lg[t] = a;
    }
    __syncthreads();
    if (t == 0) {
        float m = lg[0];
        for (int i = 1; i < CC; i++) m = fmaxf(m, lg[i]);
        float s = 0.f;
        for (int i = 0; i < CC; i++) s += expf(lg[i] - m);
        lse = m + logf(s);
    }
    __syncthreads();
    if (t < CC) out[g*CC + t] = lg[t] - lse;
}

// ---------------- launch -----------------------------------------------------
extern "C" void kernel_launch(void* const* d_in, const int* in_sizes, int n_in,
                              void* d_out, int out_size) {
    const float* x     = (const float*)d_in[0];
    const int*   ei    = (const int*)  d_in[1];   // int32 (JAX x64 disabled)
    const int*   batch = (const int*)  d_in[2];   // int32
    const float* emb   = (const float*)d_in[3];
    const float* eps   = (const float*)d_in[4];
    const float* W1    = (const float*)d_in[5];
    const float* b1    = (const float*)d_in[6];
    const float* W2    = (const float*)d_in[7];
    const float* b2    = (const float*)d_in[8];
    const float* gamma = (const float*)d_in[9];
    const float* beta  = (const float*)d_in[10];
    const float* l1w   = (const float*)d_in[11];
    const float* l1b   = (const float*)d_in[12];
    const float* l2w   = (const float*)d_in[13];
    const float* l2b   = (const float*)d_in[14];
    const float* l4w   = (const float*)d_in[15];
    const float* l4b   = (const float*)d_in[16];
    float* out = (float*)d_out;

    float *agg, *h1b, *h2b, *xs;
    cudaGetSymbolAddress((void**)&agg, g_agg);
    cudaGetSymbolAddress((void**)&h1b, g_h1);
    cudaGetSymbolAddress((void**)&h2b, g_h2);
    cudaGetSymbolAddress((void**)&xs,  g_xs);

    k_zero_pool<<<(GG*ZIN + 255)/256, 256>>>();

    for (int l = 0; l < LL; l++) {
        const float* xin = (l == 0) ? x : (xs + (l-1)*HH);
        int lda          = (l == 0) ? HH : LH;

        k_zero_bn<<<1, 256>>>();
        k_init_agg<<<(NN*(HH/4) + 255)/256, 256>>>(xin, lda, eps, l);
        k_scatter<<<(EE*32)/256, 256>>>(xin, lda, ei);
        k_gemm<false><<<(NN + 127)/128, 256>>>(agg, HH, W1 + l*HH*HH, b1 + l*HH, h1b);
        k_gemm<true> <<<(NN + 127)/128, 256>>>(h1b, HH, W2 + l*HH*HH, b2 + l*HH, h2b);
        k_bn_pool<<<(NN*(HH/4) + 255)/256, 256>>>(batch, gamma, beta, l);
    }

    k_head<<<GG, 256>>>(emb, l1w, l1b, l2w, l2b, l4w, l4b, out);
}

// round 7
// speedup vs baseline: 2.0902x; 2.0902x over previous
#include <cuda_runtime.h>

// Problem constants
#define NN   50000
#define EE   600000
#define HH   128
#define LL   4
#define GG   64
#define EMBD 64
#define CC   10
#define LH   (LL*HH)        // 512
#define ZIN  (LH+EMBD)      // 576
#define H1D  256            // 2*H
#define BN_EPS 1e-5f

// ---------------- device scratch (static, allocation-guard safe) -------------
__device__ __align__(16) float g_agg[NN*HH];   // aggregated input of current layer
__device__ __align__(16) float g_x[NN*HH];     // layer output (next layer's x)
__device__ __align__(16) float g_h2[NN*HH];    // pre-BN activations
__device__ __align__(16) float g_bnsum[2*HH];  // per-col sum / sumsq
__device__ __align__(16) float g_pool[GG*ZIN]; // pooled sums
__device__ __align__(16) float g_cnt[GG];      // nodes per graph

// ---------------- vectorized global reduction --------------------------------
__device__ __forceinline__ void red_add_v4(float* p, float4 v) {
    asm volatile("red.global.add.v4.f32 [%0], {%1,%2,%3,%4};"
                 :: "l"(p), "f"(v.x), "f"(v.y), "f"(v.z), "f"(v.w)
                 : "memory");
}

// ---------------- zero kernels ----------------------------------------------
__global__ void k_zero_pool() {
    int i = blockIdx.x * blockDim.x + threadIdx.x;
    if (i < GG*ZIN) g_pool[i] = 0.f;
    if (i < GG)     g_cnt[i]  = 0.f;
}
__global__ void k_zero_bn() {
    if (threadIdx.x < 2*HH) g_bnsum[threadIdx.x] = 0.f;
}

// ---------------- agg = (1+eps_0) * x  (layer 0 only) ------------------------
__global__ void k_init_agg(const float* __restrict__ x,
                           const float* __restrict__ eps) {
    int idx = blockIdx.x * blockDim.x + threadIdx.x;   // over NN * 32
    if (idx >= NN*(HH/4)) return;
    float s = 1.0f + eps[0];
    int row = idx >> 5;
    int c4  = (idx & 31) * 4;
    float4 v = *(const float4*)(x + (size_t)row*HH + c4);
    v.x *= s; v.y *= s; v.z *= s; v.w *= s;
    *(float4*)(g_agg + (size_t)row*HH + c4) = v;
}

// ---------------- scatter-add: agg[dst] += x[src] (warp per edge) ------------
__global__ void k_scatter(const float* __restrict__ x,
                          const int* __restrict__ ei) {
    int gtid = blockIdx.x * blockDim.x + threadIdx.x;
    int warp = gtid >> 5;
    int lane = gtid & 31;
    if (warp >= EE) return;
    int s = __ldg(ei + warp);
    int d = __ldg(ei + EE + warp);
    float4 v = *(const float4*)(x + (size_t)s*HH + lane*4);
    red_add_v4(g_agg + (size_t)d*HH + lane*4, v);
}

// ---------------- fused double SGEMM ----------------------------------------
// h1 = relu(A @ W1 + b1)  (kept in smem, full 128-wide tile per 128-row block)
// C  = relu(h1 @ W2 + b2) + per-column sum/sumsq stats
// BM=128, BN=128, BK=16, 256 threads, 8x8 per thread.
__global__ __launch_bounds__(256)
void k_gemm_fused(const float* __restrict__ A,
                  const float* __restrict__ W1, const float* __restrict__ b1,
                  const float* __restrict__ W2, const float* __restrict__ b2,
                  float* __restrict__ C) {
    extern __shared__ float smem[];
    float (*As)[128] = (float(*)[128])smem;                  // 16x128
    float (*Bs)[128] = (float(*)[128])(smem + 16*128);       // 16x128
    float (*Hs)[132] = (float(*)[132])(smem + 2*16*128);     // 128x132 (padded)
    float* ssum = smem + 2*16*128 + 128*132;                 // 128
    float* ssq  = ssum + 128;                                // 128

    int tid = threadIdx.x;
    int blockRow = blockIdx.x * 128;

    int aRow  = tid >> 2;          // 0..63
    int aCol4 = (tid & 3) * 4;     // 0,4,8,12
    int bRow  = tid >> 5;          // 0..7
    int bCol4 = (tid & 31) * 4;    // 0..124

    int tr = (tid >> 4) * 8;       // 0..120
    int tc = (tid & 15) * 8;       // 0..120

    if (tid < 128) { ssum[tid] = 0.f; ssq[tid] = 0.f; }

    float acc[8][8];
#pragma unroll
    for (int i = 0; i < 8; i++)
#pragma unroll
        for (int j = 0; j < 8; j++) acc[i][j] = 0.f;

    // -------- stage 1: acc = A @ W1 --------
    for (int k0 = 0; k0 < 128; k0 += 16) {
#pragma unroll
        for (int i = 0; i < 2; i++) {
            int r = blockRow + aRow + i*64;
            float4 v = make_float4(0.f,0.f,0.f,0.f);
            if (r < NN) v = *(const float4*)(A + (size_t)r*HH + k0 + aCol4);
            As[aCol4+0][aRow + i*64] = v.x;
            As[aCol4+1][aRow + i*64] = v.y;
            As[aCol4+2][aRow + i*64] = v.z;
            As[aCol4+3][aRow + i*64] = v.w;
        }
#pragma unroll
        for (int i = 0; i < 2; i++) {
            float4 v = *(const float4*)(W1 + (size_t)(k0 + bRow + i*8)*128 + bCol4);
            *(float4*)(&Bs[bRow + i*8][bCol4]) = v;
        }
        __syncthreads();
#pragma unroll
        for (int k = 0; k < 16; k++) {
            float ra[8], rb[8];
            float4 a0 = *(const float4*)(&As[k][tr]);
            float4 a1 = *(const float4*)(&As[k][tr+4]);
            float4 bb0 = *(const float4*)(&Bs[k][tc]);
            float4 bb1 = *(const float4*)(&Bs[k][tc+4]);
            ra[0]=a0.x; ra[1]=a0.y; ra[2]=a0.z; ra[3]=a0.w;
            ra[4]=a1.x; ra[5]=a1.y; ra[6]=a1.z; ra[7]=a1.w;
            rb[0]=bb0.x; rb[1]=bb0.y; rb[2]=bb0.z; rb[3]=bb0.w;
            rb[4]=bb1.x; rb[5]=bb1.y; rb[6]=bb1.z; rb[7]=bb1.w;
#pragma unroll
            for (int i = 0; i < 8; i++)
#pragma unroll
                for (int j = 0; j < 8; j++)
                    acc[i][j] += ra[i]*rb[j];
        }
        __syncthreads();
    }

    // epilogue 1: bias+relu, park h1 tile in smem
    {
        float rb1[8];
#pragma unroll
        for (int j = 0; j < 8; j++) rb1[j] = b1[tc+j];
#pragma unroll
        for (int i = 0; i < 8; i++) {
            float4 v0, v1;
            v0.x = fmaxf(acc[i][0] + rb1[0], 0.f);
            v0.y = fmaxf(acc[i][1] + rb1[1], 0.f);
            v0.z = fmaxf(acc[i][2] + rb1[2], 0.f);
            v0.w = fmaxf(acc[i][3] + rb1[3], 0.f);
            v1.x = fmaxf(acc[i][4] + rb1[4], 0.f);
            v1.y = fmaxf(acc[i][5] + rb1[5], 0.f);
            v1.z = fmaxf(acc[i][6] + rb1[6], 0.f);
            v1.w = fmaxf(acc[i][7] + rb1[7], 0.f);
            *(float4*)(&Hs[tr+i][tc])   = v0;
            *(float4*)(&Hs[tr+i][tc+4]) = v1;
        }
    }
    __syncthreads();

    // -------- stage 2: acc = Hs @ W2 --------
#pragma unroll
    for (int i = 0; i < 8; i++)
#pragma unroll
        for (int j = 0; j < 8; j++) acc[i][j] = 0.f;

    for (int k0 = 0; k0 < 128; k0 += 16) {
#pragma unroll
        for (int i = 0; i < 2; i++) {
            float4 v = *(const float4*)(W2 + (size_t)(k0 + bRow + i*8)*128 + bCol4);
            *(float4*)(&Bs[bRow + i*8][bCol4]) = v;
        }
        __syncthreads();
#pragma unroll
        for (int k = 0; k < 16; k++) {
            float ra[8], rb[8];
            float4 bb0 = *(const float4*)(&Bs[k][tc]);
            float4 bb1 = *(const float4*)(&Bs[k][tc+4]);
            rb[0]=bb0.x; rb[1]=bb0.y; rb[2]=bb0.z; rb[3]=bb0.w;
            rb[4]=bb1.x; rb[5]=bb1.y; rb[6]=bb1.z; rb[7]=bb1.w;
#pragma unroll
            for (int i = 0; i < 8; i++) ra[i] = Hs[tr+i][k0+k];
#pragma unroll
            for (int i = 0; i < 8; i++)
#pragma unroll
                for (int j = 0; j < 8; j++)
                    acc[i][j] += ra[i]*rb[j];
        }
        __syncthreads();
    }

    // epilogue 2: bias+relu, store C, accumulate stats
    float rb2[8];
#pragma unroll
    for (int j = 0; j < 8; j++) rb2[j] = b2[tc+j];

    float csum[8], csq[8];
#pragma unroll
    for (int j = 0; j < 8; j++) { csum[j]=0.f; csq[j]=0.f; }

#pragma unroll
    for (int i = 0; i < 8; i++) {
        int r = blockRow + tr + i;
        if (r < NN) {
            float4 v0, v1;
            float v[8];
#pragma unroll
            for (int j = 0; j < 8; j++) {
                v[j] = fmaxf(acc[i][j] + rb2[j], 0.f);
                csum[j] += v[j]; csq[j] += v[j]*v[j];
            }
            v0 = make_float4(v[0],v[1],v[2],v[3]);
            v1 = make_float4(v[4],v[5],v[6],v[7]);
            *(float4*)(C + (size_t)r*128 + tc)     = v0;
            *(float4*)(C + (size_t)r*128 + tc + 4) = v1;
        }
    }

    __syncthreads();   // ssum/ssq init visible (init was pre-mainloop; sync hit many times since)
#pragma unroll
    for (int j = 0; j < 8; j++) {
        atomicAdd(&ssum[tc+j], csum[j]);
        atomicAdd(&ssq [tc+j], csq [j]);
    }
    __syncthreads();
    if (tid < 128) {
        atomicAdd(&g_bnsum[tid],     ssum[tid]);
        atomicAdd(&g_bnsum[128+tid], ssq [tid]);
    }
}

// ---------------- BN apply + x-out + next-layer agg init + pooled reduction --
__global__ void k_bn_pool(const int* __restrict__ batch,
                          const float* __restrict__ gamma,
                          const float* __restrict__ beta,
                          const float* __restrict__ eps,
                          int l) {
    int idx = blockIdx.x * blockDim.x + threadIdx.x;  // over NN * 32
    if (idx >= NN*(HH/4)) return;
    int row = idx >> 5;
    int c4  = (idx & 31) * 4;
    const float inv = 1.0f / (float)NN;

    float4 h = *(const float4*)(g_h2 + (size_t)row*HH + c4);
    float hv[4] = {h.x, h.y, h.z, h.w};
    float vo[4];
#pragma unroll
    for (int t = 0; t < 4; t++) {
        int c = c4 + t;
        float mean = g_bnsum[c] * inv;
        float var  = g_bnsum[128+c] * inv - mean*mean;
        float rs   = rsqrtf(var + BN_EPS);
        vo[t] = (hv[t] - mean) * rs * gamma[l*HH + c] + beta[l*HH + c];
    }
    float4 o = make_float4(vo[0], vo[1], vo[2], vo[3]);
    *(float4*)(g_x + (size_t)row*HH + c4) = o;

    if (l < LL-1) {   // pre-scale next layer's self-term
        float s = 1.0f + eps[l+1];
        *(float4*)(g_agg + (size_t)row*HH + c4) =
            make_float4(vo[0]*s, vo[1]*s, vo[2]*s, vo[3]*s);
    }

    int b = batch[row];
    red_add_v4(g_pool + (size_t)b*ZIN + l*HH + c4, o);
    if (l == 0 && c4 == 0) atomicAdd(&g_cnt[b], 1.0f);
}

// ---------------- Head: MLP + log_softmax, one block per graph ---------------
__global__ __launch_bounds__(256)
void k_head(const float* __restrict__ emb,
            const float* __restrict__ l1w, const float* __restrict__ l1b,
            const float* __restrict__ l2w, const float* __restrict__ l2b,
            const float* __restrict__ l4w, const float* __restrict__ l4b,
            float* __restrict__ out) {
    __shared__ float zin[ZIN];
    __shared__ float z1[H1D];
    __shared__ float z2[HH];
    __shared__ float lg[CC];
    __shared__ float lse;

    int g = blockIdx.x, t = threadIdx.x;
    float cnt = fmaxf(g_cnt[g], 1.0f);
    for (int c = t; c < LH; c += 256) zin[c] = g_pool[g*ZIN + c] / cnt;
    if (t < EMBD) zin[LH + t] = emb[g*EMBD + t];
    __syncthreads();

    {
        float a = l1b[t];
        for (int k = 0; k < ZIN; k++) a += zin[k] * l1w[k*H1D + t];
        z1[t] = fmaxf(a, 0.f);
    }
    __syncthreads();
    if (t < HH) {
        float a = l2b[t];
        for (int k = 0; k < H1D; k++) a += z1[k] * l2w[k*HH + t];
        z2[t] = fmaxf(a, 0.f);
    }
    __syncthreads();
    if (t < CC) {
        float a = l4b[t];
        for (int k = 0; k < HH; k++) a += z2[k] * l4w[k*CC + t];
        lg[t] = a;
    }
    __syncthreads();
    if (t == 0) {
        float m = lg[0];
        for (int i = 1; i < CC; i++) m = fmaxf(m, lg[i]);
        float s = 0.f;
        for (int i = 0; i < CC; i++) s += expf(lg[i] - m);
        lse = m + logf(s);
    }
    __syncthreads();
    if (t < CC) out[g*CC + t] = lg[t] - lse;
}

// ---------------- launch -----------------------------------------------------
extern "C" void kernel_launch(void* const* d_in, const int* in_sizes, int n_in,
                              void* d_out, int out_size) {
    const float* x     = (const float*)d_in[0];
    const int*   ei    = (const int*)  d_in[1];   // int32 (JAX x64 disabled)
    const int*   batch = (const int*)  d_in[2];   // int32
    const float* emb   = (const float*)d_in[3];
    const float* eps   = (const float*)d_in[4];
    const float* W1    = (const float*)d_in[5];
    const float* b1    = (const float*)d_in[6];
    const float* W2    = (const float*)d_in[7];
    const float* b2    = (const float*)d_in[8];
    const float* gamma = (const float*)d_in[9];
    const float* beta  = (const float*)d_in[10];
    const float* l1w   = (const float*)d_in[11];
    const float* l1b   = (const float*)d_in[12];
    const float* l2w   = (const float*)d_in[13];
    const float* l2b   = (const float*)d_in[14];
    const float* l4w   = (const float*)d_in[15];
    const float* l4b   = (const float*)d_in[16];
    float* out = (float*)d_out;

    float *agg, *xb, *h2b;
    cudaGetSymbolAddress((void**)&agg, g_agg);
    cudaGetSymbolAddress((void**)&xb,  g_x);
    cudaGetSymbolAddress((void**)&h2b, g_h2);

    const int SMEM = (2*16*128 + 128*132 + 256) * 4;   // ~85 KB
    static bool attr_set = false;
    if (!attr_set) {
        cudaFuncSetAttribute(k_gemm_fused,
                             cudaFuncAttributeMaxDynamicSharedMemorySize, SMEM);
        attr_set = true;
    }

    k_zero_pool<<<(GG*ZIN + 255)/256, 256>>>();

    for (int l = 0; l < LL; l++) {
        k_zero_bn<<<1, 256>>>();
        if (l == 0) {
            k_init_agg<<<(NN*(HH/4) + 255)/256, 256>>>(x, eps);
            k_scatter<<<(EE*32)/256, 256>>>(x, ei);
        } else {
            // g_agg pre-initialized by previous k_bn_pool
            k_scatter<<<(EE*32)/256, 256>>>(xb, ei);
        }
        k_gemm_fused<<<(NN + 127)/128, 256, SMEM>>>(
            agg, W1 + l*HH*HH, b1 + l*HH, W2 + l*HH*HH, b2 + l*HH, h2b);
        k_bn_pool<<<(NN*(HH/4) + 255)/256, 256>>>(batch, gamma, beta, eps, l);
    }

    k_head<<<GG, 256>>>(emb, l1w, l1b, l2w, l2b, l4w, l4b, out);
}

// round 9
// speedup vs baseline: 2.4833x; 1.1881x over previous
#include <cuda_runtime.h>

// Problem constants
#define NN   50000
#define EE   600000
#define HH   128
#define LL   4
#define GG   64
#define EMBD 64
#define CC   10
#define LH   (LL*HH)        // 512
#define ZIN  (LH+EMBD)      // 576
#define H1D  256            // 2*H
#define BN_EPS 1e-5f

// ---------------- device scratch (static, allocation-guard safe) -------------
__device__ __align__(16) float g_agg[NN*HH];   // aggregated input of current layer
__device__ __align__(16) float g_x[NN*HH];     // layer output (next layer's x)
__device__ __align__(16) float g_h2[NN*HH];    // pre-BN activations
__device__ __align__(16) float g_bnsum[2*HH];  // per-col sum / sumsq
__device__ __align__(16) float g_pool[GG*ZIN]; // pooled sums
__device__ __align__(16) float g_cnt[GG];      // nodes per graph
// CSR (rebuilt every call — deterministic)
__device__ int g_rowptr[NN+1];
__device__ int g_cursor[NN];
__device__ int g_col[EE];

// ---------------- vectorized global reduction --------------------------------
__device__ __forceinline__ void red_add_v4(float* p, float4 v) {
    asm volatile("red.global.add.v4.f32 [%0], {%1,%2,%3,%4};"
                 :: "l"(p), "f"(v.x), "f"(v.y), "f"(v.z), "f"(v.w)
                 : "memory");
}

// ---------------- zero / CSR build kernels -----------------------------------
__global__ void k_zero_pool() {
    int i = blockIdx.x * blockDim.x + threadIdx.x;
    if (i < GG*ZIN) g_pool[i] = 0.f;
    if (i < GG)     g_cnt[i]  = 0.f;
}
__global__ void k_zero_bn() {
    if (threadIdx.x < 2*HH) g_bnsum[threadIdx.x] = 0.f;
}
__global__ void k_zero_rp() {
    int i = blockIdx.x * blockDim.x + threadIdx.x;
    if (i < NN+1) g_rowptr[i] = 0;
}
__global__ void k_deg(const int* __restrict__ ei) {
    int e = blockIdx.x * blockDim.x + threadIdx.x;
    if (e < EE) atomicAdd(&g_rowptr[ei[EE + e] + 1], 1);
}
// single-block inclusive scan over g_rowptr[0..NN]; also seeds g_cursor[i]=row start
__global__ __launch_bounds__(1024)
void k_scan() {
    __shared__ int carry;
    __shared__ int warpsum[32];
    int tid = threadIdx.x, lane = tid & 31, w = tid >> 5;
    if (tid == 0) carry = 0;
    __syncthreads();
    for (int base = 0; base < NN+1; base += 1024) {
        int i = base + tid;
        int v = (i <= NN) ? g_rowptr[i] : 0;
        // warp inclusive scan
        int s = v;
#pragma unroll
        for (int o = 1; o < 32; o <<= 1) {
            int t = __shfl_up_sync(0xFFFFFFFFu, s, o);
            if (lane >= o) s += t;
        }
        if (lane == 31) warpsum[w] = s;
        __syncthreads();
        if (w == 0) {
            int ws = warpsum[lane];
#pragma unroll
            for (int o = 1; o < 32; o <<= 1) {
                int t = __shfl_up_sync(0xFFFFFFFFu, ws, o);
                if (lane >= o) ws += t;
            }
            warpsum[lane] = ws;
        }
        __syncthreads();
        int incl = s + (w ? warpsum[w-1] : 0) + carry;
        if (i <= NN) g_rowptr[i] = incl;
        if (i <  NN) g_cursor[i] = incl;    // start of row i (exclusive prefix)
        int total = warpsum[31] + carry;
        __syncthreads();
        if (tid == 0) carry = total;
        __syncthreads();
    }
}
__global__ void k_fill(const int* __restrict__ ei) {
    int e = blockIdx.x * blockDim.x + threadIdx.x;
    if (e >= EE) return;
    int d = ei[EE + e];
    int pos = atomicAdd(&g_cursor[d], 1);
    g_col[pos] = ei[e];
}

// ---------------- gather: agg[i] = (1+eps_l)*x[i] + sum_{j in nbr(i)} x[j] ---
// one warp per row; 2-edge unrolled independent loads for MLP.
__global__ void k_gather(const float* __restrict__ x,
                         const float* __restrict__ eps, int l) {
    int gtid = blockIdx.x * blockDim.x + threadIdx.x;
    int row  = gtid >> 5;
    int lane = gtid & 31;
    if (row >= NN) return;
    const float4* x4 = (const float4*)x;
    float s = 1.0f + eps[l];
    float4 acc = x4[(size_t)row*32 + lane];
    acc.x *= s; acc.y *= s; acc.z *= s; acc.w *= s;

    int e   = g_rowptr[row];
    int end = g_rowptr[row+1];
    for (; e + 1 < end; e += 2) {
        int s0 = g_col[e], s1 = g_col[e+1];
        float4 v0 = x4[(size_t)s0*32 + lane];
        float4 v1 = x4[(size_t)s1*32 + lane];
        acc.x += v0.x + v1.x;
        acc.y += v0.y + v1.y;
        acc.z += v0.z + v1.z;
        acc.w += v0.w + v1.w;
    }
    if (e < end) {
        int s0 = g_col[e];
        float4 v0 = x4[(size_t)s0*32 + lane];
        acc.x += v0.x; acc.y += v0.y; acc.z += v0.z; acc.w += v0.w;
    }
    *(float4*)(g_agg + (size_t)row*HH + lane*4) = acc;
}

// ---------------- fused double SGEMM ----------------------------------------
// h1 = relu(A @ W1 + b1)  (kept in smem), C = relu(h1 @ W2 + b2) + BN stats.
// BM=128, BN=128, BK=16, 256 threads, 8x8 per thread.
__global__ __launch_bounds__(256)
void k_gemm_fused(const float* __restrict__ A,
                  const float* __restrict__ W1, const float* __restrict__ b1,
                  const float* __restrict__ W2, const float* __restrict__ b2,
                  float* __restrict__ C) {
    extern __shared__ float smem[];
    float (*As)[128] = (float(*)[128])smem;                  // 16x128
    float (*Bs)[128] = (float(*)[128])(smem + 16*128);       // 16x128
    float (*Hs)[132] = (float(*)[132])(smem + 2*16*128);     // 128x132 (padded)
    float* ssum = smem + 2*16*128 + 128*132;                 // 128
    float* ssq  = ssum + 128;                                // 128

    int tid = threadIdx.x;
    int blockRow = blockIdx.x * 128;

    int aRow  = tid >> 2;          // 0..63
    int aCol4 = (tid & 3) * 4;     // 0,4,8,12
    int bRow  = tid >> 5;          // 0..7
    int bCol4 = (tid & 31) * 4;    // 0..124

    int tr = (tid >> 4) * 8;       // 0..120
    int tc = (tid & 15) * 8;       // 0..120

    if (tid < 128) { ssum[tid] = 0.f; ssq[tid] = 0.f; }

    float acc[8][8];
#pragma unroll
    for (int i = 0; i < 8; i++)
#pragma unroll
        for (int j = 0; j < 8; j++) acc[i][j] = 0.f;

    // -------- stage 1: acc = A @ W1 --------
    for (int k0 = 0; k0 < 128; k0 += 16) {
#pragma unroll
        for (int i = 0; i < 2; i++) {
            int r = blockRow + aRow + i*64;
            float4 v = make_float4(0.f,0.f,0.f,0.f);
            if (r < NN) v = *(const float4*)(A + (size_t)r*HH + k0 + aCol4);
            As[aCol4+0][aRow + i*64] = v.x;
            As[aCol4+1][aRow + i*64] = v.y;
            As[aCol4+2][aRow + i*64] = v.z;
            As[aCol4+3][aRow + i*64] = v.w;
        }
#pragma unroll
        for (int i = 0; i < 2; i++) {
            float4 v = *(const float4*)(W1 + (size_t)(k0 + bRow + i*8)*128 + bCol4);
            *(float4*)(&Bs[bRow + i*8][bCol4]) = v;
        }
        __syncthreads();
#pragma unroll
        for (int k = 0; k < 16; k++) {
            float ra[8], rb[8];
            float4 a0 = *(const float4*)(&As[k][tr]);
            float4 a1 = *(const float4*)(&As[k][tr+4]);
            float4 bb0 = *(const float4*)(&Bs[k][tc]);
            float4 bb1 = *(const float4*)(&Bs[k][tc+4]);
            ra[0]=a0.x; ra[1]=a0.y; ra[2]=a0.z; ra[3]=a0.w;
            ra[4]=a1.x; ra[5]=a1.y; ra[6]=a1.z; ra[7]=a1.w;
            rb[0]=bb0.x; rb[1]=bb0.y; rb[2]=bb0.z; rb[3]=bb0.w;
            rb[4]=bb1.x; rb[5]=bb1.y; rb[6]=bb1.z; rb[7]=bb1.w;
#pragma unroll
            for (int i = 0; i < 8; i++)
#pragma unroll
                for (int j = 0; j < 8; j++)
                    acc[i][j] += ra[i]*rb[j];
        }
        __syncthreads();
    }

    // epilogue 1: bias+relu, park h1 tile in smem
    {
        float rb1[8];
#pragma unroll
        for (int j = 0; j < 8; j++) rb1[j] = b1[tc+j];
#pragma unroll
        for (int i = 0; i < 8; i++) {
            float4 v0, v1;
            v0.x = fmaxf(acc[i][0] + rb1[0], 0.f);
            v0.y = fmaxf(acc[i][1] + rb1[1], 0.f);
            v0.z = fmaxf(acc[i][2] + rb1[2], 0.f);
            v0.w = fmaxf(acc[i][3] + rb1[3], 0.f);
            v1.x = fmaxf(acc[i][4] + rb1[4], 0.f);
            v1.y = fmaxf(acc[i][5] + rb1[5], 0.f);
            v1.z = fmaxf(acc[i][6] + rb1[6], 0.f);
            v1.w = fmaxf(acc[i][7] + rb1[7], 0.f);
            *(float4*)(&Hs[tr+i][tc])   = v0;
            *(float4*)(&Hs[tr+i][tc+4]) = v1;
        }
    }
    __syncthreads();

    // -------- stage 2: acc = Hs @ W2 --------
#pragma unroll
    for (int i = 0; i < 8; i++)
#pragma unroll
        for (int j = 0; j < 8; j++) acc[i][j] = 0.f;

    for (int k0 = 0; k0 < 128; k0 += 16) {
#pragma unroll
        for (int i = 0; i < 2; i++) {
            float4 v = *(const float4*)(W2 + (size_t)(k0 + bRow + i*8)*128 + bCol4);
            *(float4*)(&Bs[bRow + i*8][bCol4]) = v;
        }
        __syncthreads();
#pragma unroll
        for (int k = 0; k < 16; k++) {
            float ra[8], rb[8];
            float4 bb0 = *(const float4*)(&Bs[k][tc]);
            float4 bb1 = *(const float4*)(&Bs[k][tc+4]);
            rb[0]=bb0.x; rb[1]=bb0.y; rb[2]=bb0.z; rb[3]=bb0.w;
            rb[4]=bb1.x; rb[5]=bb1.y; rb[6]=bb1.z; rb[7]=bb1.w;
#pragma unroll
            for (int i = 0; i < 8; i++) ra[i] = Hs[tr+i][k0+k];
#pragma unroll
            for (int i = 0; i < 8; i++)
#pragma unroll
                for (int j = 0; j < 8; j++)
                    acc[i][j] += ra[i]*rb[j];
        }
        __syncthreads();
    }

    // epilogue 2: bias+relu, store C, accumulate stats
    float rb2[8];
#pragma unroll
    for (int j = 0; j < 8; j++) rb2[j] = b2[tc+j];

    float csum[8], csq[8];
#pragma unroll
    for (int j = 0; j < 8; j++) { csum[j]=0.f; csq[j]=0.f; }

#pragma unroll
    for (int i = 0; i < 8; i++) {
        int r = blockRow + tr + i;
        if (r < NN) {
            float v[8];
#pragma unroll
            for (int j = 0; j < 8; j++) {
                v[j] = fmaxf(acc[i][j] + rb2[j], 0.f);
                csum[j] += v[j]; csq[j] += v[j]*v[j];
            }
            *(float4*)(C + (size_t)r*128 + tc)     = make_float4(v[0],v[1],v[2],v[3]);
            *(float4*)(C + (size_t)r*128 + tc + 4) = make_float4(v[4],v[5],v[6],v[7]);
        }
    }

    __syncthreads();
#pragma unroll
    for (int j = 0; j < 8; j++) {
        atomicAdd(&ssum[tc+j], csum[j]);
        atomicAdd(&ssq [tc+j], csq [j]);
    }
    __syncthreads();
    if (tid < 128) {
        atomicAdd(&g_bnsum[tid],     ssum[tid]);
        atomicAdd(&g_bnsum[128+tid], ssq [tid]);
    }
}

// ---------------- BN apply + x-out + pooled reduction ------------------------
__global__ void k_bn_pool(const int* __restrict__ batch,
                          const float* __restrict__ gamma,
                          const float* __restrict__ beta,
                          int l) {
    int idx = blockIdx.x * blockDim.x + threadIdx.x;  // over NN * 32
    if (idx >= NN*(HH/4)) return;
    int row = idx >> 5;
    int c4  = (idx & 31) * 4;
    const float inv = 1.0f / (float)NN;

    float4 h = *(const float4*)(g_h2 + (size_t)row*HH + c4);
    float hv[4] = {h.x, h.y, h.z, h.w};
    float vo[4];
#pragma unroll
    for (int t = 0; t < 4; t++) {
        int c = c4 + t;
        float mean = g_bnsum[c] * inv;
        float var  = g_bnsum[128+c] * inv - mean*mean;
        float rs   = rsqrtf(var + BN_EPS);
        vo[t] = (hv[t] - mean) * rs * gamma[l*HH + c] + beta[l*HH + c];
    }
    float4 o = make_float4(vo[0], vo[1], vo[2], vo[3]);
    *(float4*)(g_x + (size_t)row*HH + c4) = o;

    int b = batch[row];
    red_add_v4(g_pool + (size_t)b*ZIN + l*HH + c4, o);
    if (l == 0 && c4 == 0) atomicAdd(&g_cnt[b], 1.0f);
}

// ---------------- Head: MLP + log_softmax, one block per graph ---------------
__global__ __launch_bounds__(256)
void k_head(const float* __restrict__ emb,
            const float* __restrict__ l1w, const float* __restrict__ l1b,
            const float* __restrict__ l2w, const float* __restrict__ l2b,
            const float* __restrict__ l4w, const float* __restrict__ l4b,
            float* __restrict__ out) {
    __shared__ float zin[ZIN];
    __shared__ float z1[H1D];
    __shared__ float z2[HH];
    __shared__ float lg[CC];
    __shared__ float lse;

    int g = blockIdx.x, t = threadIdx.x;
    float cnt = fmaxf(g_cnt[g], 1.0f);
    for (int c = t; c < LH; c += 256) zin[c] = g_pool[g*ZIN + c] / cnt;
    if (t < EMBD) zin[LH + t] = emb[g*EMBD + t];
    __syncthreads();

    {
        float a = l1b[t];
        for (int k = 0; k < ZIN; k++) a += zin[k] * l1w[k*H1D + t];
        z1[t] = fmaxf(a, 0.f);
    }
    __syncthreads();
    if (t < HH) {
        float a = l2b[t];
        for (int k = 0; k < H1D; k++) a += z1[k] * l2w[k*HH + t];
        z2[t] = fmaxf(a, 0.f);
    }
    __syncthreads();
    if (t < CC) {
        float a = l4b[t];
        for (int k = 0; k < HH; k++) a += z2[k] * l4w[k*CC + t];
        lg[t] = a;
    }
    __syncthreads();
    if (t == 0) {
        float m = lg[0];
        for (int i = 1; i < CC; i++) m = fmaxf(m, lg[i]);
        float s = 0.f;
        for (int i = 0; i < CC; i++) s += expf(lg[i] - m);
        lse = m + logf(s);
    }
    __syncthreads();
    if (t < CC) out[g*CC + t] = lg[t] - lse;
}

// ---------------- launch -----------------------------------------------------
extern "C" void kernel_launch(void* const* d_in, const int* in_sizes, int n_in,
                              void* d_out, int out_size) {
    const float* x     = (const float*)d_in[0];
    const int*   ei    = (const int*)  d_in[1];   // int32 (JAX x64 disabled)
    const int*   batch = (const int*)  d_in[2];   // int32
    const float* emb   = (const float*)d_in[3];
    const float* eps   = (const float*)d_in[4];
    const float* W1    = (const float*)d_in[5];
    const float* b1    = (const float*)d_in[6];
    const float* W2    = (const float*)d_in[7];
    const float* b2    = (const float*)d_in[8];
    const float* gamma = (const float*)d_in[9];
    const float* beta  = (const float*)d_in[10];
    const float* l1w   = (const float*)d_in[11];
    const float* l1b   = (const float*)d_in[12];
    const float* l2w   = (const float*)d_in[13];
    const float* l2b   = (const float*)d_in[14];
    const float* l4w   = (const float*)d_in[15];
    const float* l4b   = (const float*)d_in[16];
    float* out = (float*)d_out;

    float *agg, *xb, *h2b;
    cudaGetSymbolAddress((void**)&agg, g_agg);
    cudaGetSymbolAddress((void**)&xb,  g_x);
    cudaGetSymbolAddress((void**)&h2b, g_h2);

    const int SMEM = (2*16*128 + 128*132 + 256) * 4;   // ~85 KB
    static bool attr_set = false;
    if (!attr_set) {
        cudaFuncSetAttribute(k_gemm_fused,
                             cudaFuncAttributeMaxDynamicSharedMemorySize, SMEM);
        attr_set = true;
    }

    // ---- CSR build (every call; deterministic) ----
    k_zero_rp<<<(NN+1 + 255)/256, 256>>>();
    k_deg<<<(EE + 255)/256, 256>>>(ei);
    k_scan<<<1, 1024>>>();
    k_fill<<<(EE + 255)/256, 256>>>(ei);

    k_zero_pool<<<(GG*ZIN + 255)/256, 256>>>();

    for (int l = 0; l < LL; l++) {
        k_zero_bn<<<1, 256>>>();
        const float* xin = (l == 0) ? x : xb;
        k_gather<<<(NN*32 + 255)/256, 256>>>(xin, eps, l);
        k_gemm_fused<<<(NN + 127)/128, 256, SMEM>>>(
            agg, W1 + l*HH*HH, b1 + l*HH, W2 + l*HH*HH, b2 + l*HH, h2b);
        k_bn_pool<<<(NN*(HH/4) + 255)/256, 256>>>(batch, gamma, beta, l);
    }

    k_head<<<GG, 256>>>(emb, l1w, l1b, l2w, l2b, l4w, l4b, out);
}